// round 1
// baseline (speedup 1.0000x reference)
#include <cuda_runtime.h>
#include <cuda_bf16.h>

// Problem dims (fixed): B=4, S=256, D_MODEL=2048, H=256, HEAD_DIM=8
// M = B*S = 1024 rows, K = N = 2048.
#define M_DIM 1024
#define N_DIM 2048
#define K_DIM 2048
#define HEADS 256
#define HDIM  8

// ---------------- scratch (no cudaMalloc allowed) ----------------
__device__ float g_q  [M_DIM * N_DIM];
__device__ float g_k  [M_DIM * N_DIM];
__device__ float g_v  [M_DIM * N_DIM];
__device__ float g_att[M_DIM * N_DIM];

__device__ __forceinline__ float* devbuf(int sel) {
    switch (sel) {
        case 0: return g_q;
        case 1: return g_k;
        case 2: return g_v;
        default: return g_att;
    }
}

// ---------------- SGEMM: C = A @ W + bias ----------------
// A: [M,K] row-major, W: [K,N] row-major, C: [M,N] row-major.
// 128x128 block, BK=8, 256 threads, 8x8 per-thread micro-tile.
#define BM 128
#define BN 128
#define BK 8
#define TM 8
#define TN 8

__global__ __launch_bounds__(256)
void sgemm_bias(const float* __restrict__ Aext,
                const float* __restrict__ W,
                const float* __restrict__ bias,
                float* __restrict__ Cext,
                int aSel, int cSel)
{
    const float* A = Aext ? Aext : devbuf(aSel);
    float*       C = Cext ? Cext : devbuf(cSel);

    __shared__ float As[BK][BM];   // transposed A tile
    __shared__ float Bs[BK][BN];

    const int tid = threadIdx.x;
    const int tx = tid % 16;       // column group
    const int ty = tid / 16;       // row group
    const int bm = blockIdx.y * BM;
    const int bn = blockIdx.x * BN;

    // A tile load: 128x8 floats, each thread one float4
    const int aRow = tid >> 1;            // 0..127
    const int aCol = (tid & 1) * 4;       // 0 or 4
    // B tile load: 8x128 floats, each thread one float4
    const int bRow = tid >> 5;            // 0..7
    const int bCol = (tid & 31) * 4;      // 0..124

    const float* Aptr = A + (size_t)(bm + aRow) * K_DIM + aCol;
    const float* Bptr = W + (size_t)bRow * N_DIM + bn + bCol;

    float acc[TM][TN];
    #pragma unroll
    for (int i = 0; i < TM; i++)
        #pragma unroll
        for (int j = 0; j < TN; j++) acc[i][j] = 0.0f;

    for (int k0 = 0; k0 < K_DIM; k0 += BK) {
        float4 av = *(const float4*)(Aptr + k0);
        float4 bv = *(const float4*)(Bptr + (size_t)k0 * N_DIM);
        As[aCol + 0][aRow] = av.x;
        As[aCol + 1][aRow] = av.y;
        As[aCol + 2][aRow] = av.z;
        As[aCol + 3][aRow] = av.w;
        *(float4*)&Bs[bRow][bCol] = bv;
        __syncthreads();

        #pragma unroll
        for (int k = 0; k < BK; k++) {
            float af[TM], bf[TN];
            #pragma unroll
            for (int i = 0; i < TM; i++) af[i] = As[k][ty * TM + i];
            #pragma unroll
            for (int j = 0; j < TN; j++) bf[j] = Bs[k][tx * TN + j];
            #pragma unroll
            for (int i = 0; i < TM; i++)
                #pragma unroll
                for (int j = 0; j < TN; j++)
                    acc[i][j] = fmaf(af[i], bf[j], acc[i][j]);
        }
        __syncthreads();
    }

    // epilogue: add bias, vectorized stores
    float4 bb0 = *(const float4*)(bias + bn + tx * TN);
    float4 bb1 = *(const float4*)(bias + bn + tx * TN + 4);
    #pragma unroll
    for (int i = 0; i < TM; i++) {
        const size_t row = bm + ty * TM + i;
        float4 r0, r1;
        r0.x = acc[i][0] + bb0.x;  r0.y = acc[i][1] + bb0.y;
        r0.z = acc[i][2] + bb0.z;  r0.w = acc[i][3] + bb0.w;
        r1.x = acc[i][4] + bb1.x;  r1.y = acc[i][5] + bb1.y;
        r1.z = acc[i][6] + bb1.z;  r1.w = acc[i][7] + bb1.w;
        *(float4*)&C[row * N_DIM + bn + tx * TN]     = r0;
        *(float4*)&C[row * N_DIM + bn + tx * TN + 4] = r1;
    }
}

// ---------------- fast exp (avoid MUFU bottleneck: 67M exps) ----------------
// exp(x) = 2^(x*log2e); round-to-nearest via magic constant, degree-5 poly for
// 2^f on [-0.5, 0.5] (Taylor of e^{f ln2}, rel err ~2e-6).
__device__ __forceinline__ float fast_exp(float x)
{
    float z  = x * 1.4426950408889634f;
    float fi = z + 12582912.0f;               // 1.5 * 2^23: round to nearest int
    int   n  = __float_as_int(fi) - 0x4B400000;
    float f  = z - (fi - 12582912.0f);        // frac in [-0.5, 0.5]
    float p  = 1.3333558146e-3f;
    p = fmaf(p, f, 9.6181291918e-3f);
    p = fmaf(p, f, 5.5504108664e-2f);
    p = fmaf(p, f, 2.4022650695e-1f);
    p = fmaf(p, f, 6.9314718056e-1f);
    p = fmaf(p, f, 1.0f);
    return __int_as_float(__float_as_int(p) + (n << 23));
}

// ---------------- per-(b,s) head-mixing attention ----------------
// One block per (b,s) row m. Thread t = head h. scores[h,g] = q_h . k_g / sqrt(8),
// softmax over g (shift-invariant; logits are O(1), no max subtraction needed),
// out[h,:] = sum_g p[g] * v_g / sum_g p[g].
__global__ __launch_bounds__(256)
void attention_kernel()
{
    const int m = blockIdx.x;      // 0..1023
    const int t = threadIdx.x;     // head index 0..255

    __shared__ float ks[N_DIM];
    __shared__ float vs[N_DIM];

    const float* qrow = g_q + (size_t)m * N_DIM;
    const float* krow = g_k + (size_t)m * N_DIM;
    const float* vrow = g_v + (size_t)m * N_DIM;

    // cooperative load of k and v rows (8 floats per thread)
    *(float4*)&ks[t * 8]     = *(const float4*)&krow[t * 8];
    *(float4*)&ks[t * 8 + 4] = *(const float4*)&krow[t * 8 + 4];
    *(float4*)&vs[t * 8]     = *(const float4*)&vrow[t * 8];
    *(float4*)&vs[t * 8 + 4] = *(const float4*)&vrow[t * 8 + 4];

    const float scale = 0.35355339059327373f;   // 1/sqrt(8)
    float4 q0 = *(const float4*)&qrow[t * 8];
    float4 q1 = *(const float4*)&qrow[t * 8 + 4];
    q0.x *= scale; q0.y *= scale; q0.z *= scale; q0.w *= scale;
    q1.x *= scale; q1.y *= scale; q1.z *= scale; q1.w *= scale;

    __syncthreads();

    float sum = 0.0f;
    float4 o0 = {0.f, 0.f, 0.f, 0.f};
    float4 o1 = {0.f, 0.f, 0.f, 0.f};

    #pragma unroll 4
    for (int g = 0; g < HEADS; g++) {
        float4 k0 = *(const float4*)&ks[g * 8];      // broadcast: conflict-free
        float4 k1 = *(const float4*)&ks[g * 8 + 4];
        float s;
        s = q0.x * k0.x;
        s = fmaf(q0.y, k0.y, s);
        s = fmaf(q0.z, k0.z, s);
        s = fmaf(q0.w, k0.w, s);
        s = fmaf(q1.x, k1.x, s);
        s = fmaf(q1.y, k1.y, s);
        s = fmaf(q1.z, k1.z, s);
        s = fmaf(q1.w, k1.w, s);
        float p = fast_exp(s);
        sum += p;
        float4 v0 = *(const float4*)&vs[g * 8];
        float4 v1 = *(const float4*)&vs[g * 8 + 4];
        o0.x = fmaf(p, v0.x, o0.x);  o0.y = fmaf(p, v0.y, o0.y);
        o0.z = fmaf(p, v0.z, o0.z);  o0.w = fmaf(p, v0.w, o0.w);
        o1.x = fmaf(p, v1.x, o1.x);  o1.y = fmaf(p, v1.y, o1.y);
        o1.z = fmaf(p, v1.z, o1.z);  o1.w = fmaf(p, v1.w, o1.w);
    }

    const float inv = 1.0f / sum;
    o0.x *= inv; o0.y *= inv; o0.z *= inv; o0.w *= inv;
    o1.x *= inv; o1.y *= inv; o1.z *= inv; o1.w *= inv;
    *(float4*)&g_att[(size_t)m * N_DIM + t * 8]     = o0;
    *(float4*)&g_att[(size_t)m * N_DIM + t * 8 + 4] = o1;
}

// ---------------- launch ----------------
extern "C" void kernel_launch(void* const* d_in, const int* in_sizes, int n_in,
                              void* d_out, int out_size)
{
    const float* x  = (const float*)d_in[0];
    // d_in[1] = phase_shift: mathematically dead (cos^2 + sin^2 = 1 in the
    // real score; imaginary softmax is discarded by the reference).
    const float* Wq = (const float*)d_in[2];
    const float* bq = (const float*)d_in[3];
    const float* Wk = (const float*)d_in[4];
    const float* bk = (const float*)d_in[5];
    const float* Wv = (const float*)d_in[6];
    const float* bv = (const float*)d_in[7];
    const float* Wo = (const float*)d_in[8];
    const float* bo = (const float*)d_in[9];
    float* out = (float*)d_out;

    dim3 grid(N_DIM / BN, M_DIM / BM);   // (16, 8) = 128 blocks

    sgemm_bias<<<grid, 256>>>(x, Wq, bq, nullptr, -1, 0);
    sgemm_bias<<<grid, 256>>>(x, Wk, bk, nullptr, -1, 1);
    sgemm_bias<<<grid, 256>>>(x, Wv, bv, nullptr, -1, 2);
    attention_kernel<<<M_DIM, 256>>>();
    sgemm_bias<<<grid, 256>>>(nullptr, Wo, bo, out, 3, -1);
}

// round 3
// speedup vs baseline: 3.1306x; 3.1306x over previous
#include <cuda_runtime.h>
#include <cuda_bf16.h>

// Dims fixed: B=4, S=256, D_MODEL=2048, H=256, HEAD_DIM=8; M = B*S = 1024.
#define M_DIM 1024
#define N_DIM 2048
#define K_DIM 2048
#define HEADS 256

// ---------------- scratch ----------------
__device__ float g_q  [M_DIM * N_DIM];
__device__ float g_k  [M_DIM * N_DIM];
__device__ float g_v  [M_DIM * N_DIM];
__device__ float g_att[M_DIM * N_DIM];

// ---------------- tf32 tensor-core GEMM ----------------
// C[M,N] = A[M,K] @ W[K,N] + bias, all row-major fp32 in gmem, tf32 compute.
// Block tile 128x128, BK=16, 256 threads (8 warps: 2x4), warp tile 64x32,
// per-warp 4x4 m16n8k8 atoms. Double-buffered smem, padded rows (+8 floats)
// so fragment LDS is bank-conflict-free.
#define BM 128
#define BN 128
#define BK 16
#define ASTR (BM + 8)   // 136 floats: stride%32==8 -> conflict-free frag loads
#define BSTR (BN + 8)

__device__ __forceinline__ unsigned f2tf(float x) {
    unsigned r;
    asm("cvt.rna.tf32.f32 %0, %1;" : "=r"(r) : "f"(x));
    return r;
}

__device__ __forceinline__ void mma_tf32(float* c,
                                         unsigned a0, unsigned a1, unsigned a2, unsigned a3,
                                         unsigned b0, unsigned b1)
{
    asm volatile(
        "mma.sync.aligned.m16n8k8.row.col.f32.tf32.tf32.f32 "
        "{%0,%1,%2,%3}, {%4,%5,%6,%7}, {%8,%9}, {%0,%1,%2,%3};\n"
        : "+f"(c[0]), "+f"(c[1]), "+f"(c[2]), "+f"(c[3])
        : "r"(a0), "r"(a1), "r"(a2), "r"(a3), "r"(b0), "r"(b1));
}

__device__ __forceinline__ void gemm_body(const float* __restrict__ A,
                                          const float* __restrict__ W,
                                          const float* __restrict__ bias,
                                          float* __restrict__ C)
{
    __shared__ float As[2][BK][ASTR];   // As[buf][k][m]
    __shared__ float Bs[2][BK][BSTR];   // Bs[buf][k][n]

    const int tid  = threadIdx.x;
    const int lane = tid & 31;
    const int wid  = tid >> 5;
    const int wm   = wid >> 2;          // 0..1 -> warp M base = wm*64
    const int wn   = wid & 3;           // 0..3 -> warp N base = wn*32
    const int lr   = lane >> 2;         // 0..7
    const int lc   = lane & 3;          // 0..3
    const int bm   = blockIdx.y * BM;
    const int bn   = blockIdx.x * BN;

    // A gmem loader: rows arow, arow+64; 4 contiguous k per thread (coalesced float4)
    const int arow = tid >> 2;          // 0..63
    const int ac4  = (tid & 3) * 4;     // 0,4,8,12
    // B gmem loader: rows brow, brow+8; 4 contiguous n (coalesced float4)
    const int brow = tid >> 5;          // 0..7
    const int bc4  = (tid & 31) * 4;    // 0..124

    const float* Aptr = A + (size_t)(bm + arow) * K_DIM + ac4;
    const float* Wptr = W + (size_t)brow * N_DIM + bn + bc4;

    float c[4][4][4];
    #pragma unroll
    for (int i = 0; i < 4; i++)
        #pragma unroll
        for (int j = 0; j < 4; j++)
            #pragma unroll
            for (int r = 0; r < 4; r++) c[i][j][r] = 0.0f;

    float4 ra0, ra1, rb0, rb1;

    // prologue: tile 0 -> buf 0
    ra0 = *(const float4*)(Aptr);
    ra1 = *(const float4*)(Aptr + (size_t)64 * K_DIM);
    rb0 = *(const float4*)(Wptr);
    rb1 = *(const float4*)(Wptr + (size_t)8 * N_DIM);
    {
        As[0][ac4 + 0][arow] = __uint_as_float(f2tf(ra0.x));
        As[0][ac4 + 1][arow] = __uint_as_float(f2tf(ra0.y));
        As[0][ac4 + 2][arow] = __uint_as_float(f2tf(ra0.z));
        As[0][ac4 + 3][arow] = __uint_as_float(f2tf(ra0.w));
        As[0][ac4 + 0][arow + 64] = __uint_as_float(f2tf(ra1.x));
        As[0][ac4 + 1][arow + 64] = __uint_as_float(f2tf(ra1.y));
        As[0][ac4 + 2][arow + 64] = __uint_as_float(f2tf(ra1.z));
        As[0][ac4 + 3][arow + 64] = __uint_as_float(f2tf(ra1.w));
        float4 t0, t1;
        t0.x = __uint_as_float(f2tf(rb0.x)); t0.y = __uint_as_float(f2tf(rb0.y));
        t0.z = __uint_as_float(f2tf(rb0.z)); t0.w = __uint_as_float(f2tf(rb0.w));
        t1.x = __uint_as_float(f2tf(rb1.x)); t1.y = __uint_as_float(f2tf(rb1.y));
        t1.z = __uint_as_float(f2tf(rb1.z)); t1.w = __uint_as_float(f2tf(rb1.w));
        *(float4*)&Bs[0][brow][bc4]     = t0;
        *(float4*)&Bs[0][brow + 8][bc4] = t1;
    }
    __syncthreads();

    const int NK = K_DIM / BK;   // 128
    for (int kt = 0; kt < NK; kt++) {
        const int cur = kt & 1;

        if (kt + 1 < NK) {
            const int k0 = (kt + 1) * BK;
            ra0 = *(const float4*)(Aptr + k0);
            ra1 = *(const float4*)(Aptr + (size_t)64 * K_DIM + k0);
            rb0 = *(const float4*)(Wptr + (size_t)k0 * N_DIM);
            rb1 = *(const float4*)(Wptr + (size_t)(k0 + 8) * N_DIM);
        }

        // compute: two k8 steps on buffer `cur`
        #pragma unroll
        for (int ks = 0; ks < 2; ks++) {
            const int k = ks * 8;
            unsigned af[4][4], bf[4][2];
            #pragma unroll
            for (int i = 0; i < 4; i++) {
                const int m0 = wm * 64 + i * 16 + lr;
                af[i][0] = __float_as_uint(As[cur][k + lc    ][m0]);
                af[i][1] = __float_as_uint(As[cur][k + lc    ][m0 + 8]);
                af[i][2] = __float_as_uint(As[cur][k + lc + 4][m0]);
                af[i][3] = __float_as_uint(As[cur][k + lc + 4][m0 + 8]);
            }
            #pragma unroll
            for (int j = 0; j < 4; j++) {
                const int n0 = wn * 32 + j * 8 + lr;
                bf[j][0] = __float_as_uint(Bs[cur][k + lc    ][n0]);
                bf[j][1] = __float_as_uint(Bs[cur][k + lc + 4][n0]);
            }
            #pragma unroll
            for (int i = 0; i < 4; i++)
                #pragma unroll
                for (int j = 0; j < 4; j++)
                    mma_tf32(c[i][j], af[i][0], af[i][1], af[i][2], af[i][3],
                             bf[j][0], bf[j][1]);
        }

        if (kt + 1 < NK) {
            const int nb = cur ^ 1;
            As[nb][ac4 + 0][arow] = __uint_as_float(f2tf(ra0.x));
            As[nb][ac4 + 1][arow] = __uint_as_float(f2tf(ra0.y));
            As[nb][ac4 + 2][arow] = __uint_as_float(f2tf(ra0.z));
            As[nb][ac4 + 3][arow] = __uint_as_float(f2tf(ra0.w));
            As[nb][ac4 + 0][arow + 64] = __uint_as_float(f2tf(ra1.x));
            As[nb][ac4 + 1][arow + 64] = __uint_as_float(f2tf(ra1.y));
            As[nb][ac4 + 2][arow + 64] = __uint_as_float(f2tf(ra1.z));
            As[nb][ac4 + 3][arow + 64] = __uint_as_float(f2tf(ra1.w));
            float4 t0, t1;
            t0.x = __uint_as_float(f2tf(rb0.x)); t0.y = __uint_as_float(f2tf(rb0.y));
            t0.z = __uint_as_float(f2tf(rb0.z)); t0.w = __uint_as_float(f2tf(rb0.w));
            t1.x = __uint_as_float(f2tf(rb1.x)); t1.y = __uint_as_float(f2tf(rb1.y));
            t1.z = __uint_as_float(f2tf(rb1.z)); t1.w = __uint_as_float(f2tf(rb1.w));
            *(float4*)&Bs[nb][brow][bc4]     = t0;
            *(float4*)&Bs[nb][brow + 8][bc4] = t1;
            __syncthreads();
        }
    }

    // epilogue: bias + store (c0,c1 and c2,c3 are adjacent columns -> float2)
    #pragma unroll
    for (int i = 0; i < 4; i++) {
        const int row0 = bm + wm * 64 + i * 16 + lr;
        #pragma unroll
        for (int j = 0; j < 4; j++) {
            const int col = bn + wn * 32 + j * 8 + 2 * lc;
            float2 bb = *(const float2*)(bias + col);
            float2 r0, r1;
            r0.x = c[i][j][0] + bb.x;  r0.y = c[i][j][1] + bb.y;
            r1.x = c[i][j][2] + bb.x;  r1.y = c[i][j][3] + bb.y;
            *(float2*)&C[(size_t)row0 * N_DIM + col]       = r0;
            *(float2*)&C[(size_t)(row0 + 8) * N_DIM + col] = r1;
        }
    }
}

__global__ __launch_bounds__(256, 1)
void qkv_gemm(const float* __restrict__ x,
              const float* __restrict__ Wq, const float* __restrict__ bq,
              const float* __restrict__ Wk, const float* __restrict__ bk,
              const float* __restrict__ Wv, const float* __restrict__ bv)
{
    const float* W; const float* b; float* C;
    if (blockIdx.z == 0)      { W = Wq; b = bq; C = g_q; }
    else if (blockIdx.z == 1) { W = Wk; b = bk; C = g_k; }
    else                      { W = Wv; b = bv; C = g_v; }
    gemm_body(x, W, b, C);
}

__global__ __launch_bounds__(256, 1)
void o_gemm(const float* __restrict__ Wo, const float* __restrict__ bo,
            float* __restrict__ out)
{
    gemm_body(g_att, Wo, bo, out);
}

// ---------------- fast exp ----------------
__device__ __forceinline__ float fast_exp(float x)
{
    float z  = x * 1.4426950408889634f;
    float fi = z + 12582912.0f;               // round-to-nearest-int magic
    int   n  = __float_as_int(fi) - 0x4B400000;
    float f  = z - (fi - 12582912.0f);
    float p  = 1.3333558146e-3f;
    p = fmaf(p, f, 9.6181291918e-3f);
    p = fmaf(p, f, 5.5504108664e-2f);
    p = fmaf(p, f, 2.4022650695e-1f);
    p = fmaf(p, f, 6.9314718056e-1f);
    p = fmaf(p, f, 1.0f);
    return __int_as_float(__float_as_int(p) + (n << 23));
}

// ---------------- per-(b,s) head-mixing attention ----------------
// phase_shift is analytically dead (cos^2+sin^2 = 1; imaginary softmax discarded).
__global__ __launch_bounds__(256)
void attention_kernel()
{
    const int m = blockIdx.x;
    const int t = threadIdx.x;

    __shared__ float ks[N_DIM];
    __shared__ float vs[N_DIM];

    const float* qrow = g_q + (size_t)m * N_DIM;
    const float* krow = g_k + (size_t)m * N_DIM;
    const float* vrow = g_v + (size_t)m * N_DIM;

    *(float4*)&ks[t * 8]     = *(const float4*)&krow[t * 8];
    *(float4*)&ks[t * 8 + 4] = *(const float4*)&krow[t * 8 + 4];
    *(float4*)&vs[t * 8]     = *(const float4*)&vrow[t * 8];
    *(float4*)&vs[t * 8 + 4] = *(const float4*)&vrow[t * 8 + 4];

    const float scale = 0.35355339059327373f;   // 1/sqrt(8)
    float4 q0 = *(const float4*)&qrow[t * 8];
    float4 q1 = *(const float4*)&qrow[t * 8 + 4];
    q0.x *= scale; q0.y *= scale; q0.z *= scale; q0.w *= scale;
    q1.x *= scale; q1.y *= scale; q1.z *= scale; q1.w *= scale;

    __syncthreads();

    float sum = 0.0f;
    float4 o0 = {0.f, 0.f, 0.f, 0.f};
    float4 o1 = {0.f, 0.f, 0.f, 0.f};

    #pragma unroll 4
    for (int g = 0; g < HEADS; g++) {
        float4 k0 = *(const float4*)&ks[g * 8];
        float4 k1 = *(const float4*)&ks[g * 8 + 4];
        float s;
        s = q0.x * k0.x;
        s = fmaf(q0.y, k0.y, s);
        s = fmaf(q0.z, k0.z, s);
        s = fmaf(q0.w, k0.w, s);
        s = fmaf(q1.x, k1.x, s);
        s = fmaf(q1.y, k1.y, s);
        s = fmaf(q1.z, k1.z, s);
        s = fmaf(q1.w, k1.w, s);
        float p = fast_exp(s);
        sum += p;
        float4 v0 = *(const float4*)&vs[g * 8];
        float4 v1 = *(const float4*)&vs[g * 8 + 4];
        o0.x = fmaf(p, v0.x, o0.x);  o0.y = fmaf(p, v0.y, o0.y);
        o0.z = fmaf(p, v0.z, o0.z);  o0.w = fmaf(p, v0.w, o0.w);
        o1.x = fmaf(p, v1.x, o1.x);  o1.y = fmaf(p, v1.y, o1.y);
        o1.z = fmaf(p, v1.z, o1.z);  o1.w = fmaf(p, v1.w, o1.w);
    }

    const float inv = 1.0f / sum;
    o0.x *= inv; o0.y *= inv; o0.z *= inv; o0.w *= inv;
    o1.x *= inv; o1.y *= inv; o1.z *= inv; o1.w *= inv;
    *(float4*)&g_att[(size_t)m * N_DIM + t * 8]     = o0;
    *(float4*)&g_att[(size_t)m * N_DIM + t * 8 + 4] = o1;
}

// ---------------- launch ----------------
extern "C" void kernel_launch(void* const* d_in, const int* in_sizes, int n_in,
                              void* d_out, int out_size)
{
    const float* x  = (const float*)d_in[0];
    // d_in[1] = phase_shift: dead.
    const float* Wq = (const float*)d_in[2];
    const float* bq = (const float*)d_in[3];
    const float* Wk = (const float*)d_in[4];
    const float* bk = (const float*)d_in[5];
    const float* Wv = (const float*)d_in[6];
    const float* bv = (const float*)d_in[7];
    const float* Wo = (const float*)d_in[8];
    const float* bo = (const float*)d_in[9];
    float* out = (float*)d_out;

    dim3 gQKV(N_DIM / BN, M_DIM / BM, 3);   // 16 x 8 x 3 = 384 blocks
    dim3 gO  (N_DIM / BN, M_DIM / BM, 1);

    qkv_gemm<<<gQKV, 256>>>(x, Wq, bq, Wk, bk, Wv, bv);
    attention_kernel<<<M_DIM, 256>>>();
    o_gemm<<<gO, 256>>>(Wo, bo, out);
}